// round 9
// baseline (speedup 1.0000x reference)
#include <cuda_runtime.h>
#include <math.h>
#include <stdint.h>

#define BB 8
#define SS 1024
#define EE 256
#define HH 256
#define H2 512
#define COUT 64
#define MROWS (BB*SS)   /* 8192 */

// ---------------- scratch (static __device__ arrays; no cudaMalloc) ----------------
__device__ __align__(16) float g_x[MROWS*EE];
__device__ __align__(16) float g_xgf[MROWS*3*HH];
__device__ __align__(16) float g_xgb[MROWS*3*HH];
__device__ __align__(16) float g_bigru[MROWS*H2];
__device__ __align__(16) float g_hiddencat[BB*H2];
__device__ __align__(16) float g_xgu[MROWS*3*H2];
__device__ __align__(16) float g_U[MROWS*H2];
__device__ __align__(16) float g_energy[BB*SS*SS];
__device__ __align__(16) float g_context[MROWS*H2];
__device__ __align__(16) float g_cfc[MROWS*H2];
__device__ __align__(16) float g_gate[MROWS*H2];
__device__ __align__(16) float g_ft[MROWS*H2];
__device__ __align__(16) float g_hu[2][BB*H2];

// ---------------- barrier state for uni (proven sense-reversing, per-group lines) ---
__device__ __align__(128) unsigned g_bar_count[16][32];
__device__ __align__(128) unsigned g_bar_gen[16][32];

__device__ __forceinline__ void grid_barrier(unsigned nctas, int idx) {
    __syncthreads();
    if (threadIdx.x == 0) {
        __threadfence();   // release
        unsigned my = *((volatile unsigned*)&g_bar_gen[idx][0]);
        unsigned t  = atomicAdd(&g_bar_count[idx][0], 1u);
        if (t == nctas - 1u) {
            g_bar_count[idx][0] = 0u;
            __threadfence();
            atomicExch(&g_bar_gen[idx][0], my + 1u);
        } else {
            while (*((volatile unsigned*)&g_bar_gen[idx][0]) == my) { }
            __threadfence(); // acquire
        }
    }
    __syncthreads();
}

// ---------------- cluster helpers ----------------
__device__ __forceinline__ uint32_t smem_u32_(const void* p) {
    uint32_t a;
    asm("{ .reg .u64 t; cvta.to.shared.u64 t, %1; cvt.u32.u64 %0, t; }" : "=r"(a) : "l"(p));
    return a;
}
__device__ __forceinline__ uint32_t mapa_u32_(uint32_t addr, uint32_t rank) {
    uint32_t r;
    asm("mapa.shared::cluster.u32 %0, %1, %2;" : "=r"(r) : "r"(addr), "r"(rank));
    return r;
}
__device__ __forceinline__ float ld_cluster_f32_(uint32_t addr) {
    float v;
    asm volatile("ld.shared::cluster.f32 %0, [%1];" : "=f"(v) : "r"(addr));
    return v;
}
__device__ __forceinline__ void cluster_sync_() {
    asm volatile("barrier.cluster.arrive.aligned;" ::: "memory");
    asm volatile("barrier.cluster.wait.aligned;"   ::: "memory");
}

// fast gate functions (|err| ~1e-7, threshold is 1e-3)
__device__ __forceinline__ float fsigmoid_(float x) { return 1.f/(1.f + __expf(-x)); }
__device__ __forceinline__ float ftanh_(float x)    { return 1.f - 2.f/(__expf(2.f*x) + 1.f); }
__device__ __forceinline__ float sigmoidf_(float x) { return 1.f/(1.f + expf(-x)); }

// ---------------- embedding gather ----------------
__global__ void embed_kernel(const int* __restrict__ tok, const float* __restrict__ emb) {
    int m = blockIdx.x;
    int e = threadIdx.x;                       // EE == 256 == blockDim
    g_x[m*EE + e] = emb[(long long)tok[m]*EE + e];
}

// ---------------- fp32 GEMM, double-buffered, 2 CTAs/SM: C = A @ op(W) + bias -------
template<bool TRANS_W, bool ACCUM>
__global__ void __launch_bounds__(256, 2) gemm_kernel(
    const float* __restrict__ A, const float* __restrict__ W,
    const float* __restrict__ bias, float* __restrict__ C,
    int M, int N, int K,
    long long sA, long long sW, long long sC)
{
    constexpr int BM = 128, BN = 128, BK = 16;
    __shared__ float As[2][BK][BM];
    __shared__ float Ws[2][BK][BN];

    A += (long long)blockIdx.z * sA;
    W += (long long)blockIdx.z * sW;
    C += (long long)blockIdx.z * sC;

    const int m0 = blockIdx.y * BM, n0 = blockIdx.x * BN;
    const int tid = threadIdx.x;
    const int tx = tid & 15, ty = tid >> 4;

    float4 ra[2], rw[2];

    auto ldA = [&](int k0) {
#pragma unroll
        for (int it = 0; it < 2; it++) {
            int idx = tid + it*256;
            int m = idx >> 2, k4 = (idx & 3) * 4;
            ra[it] = *reinterpret_cast<const float4*>(&A[(long long)(m0 + m)*K + k0 + k4]);
        }
    };
    auto stA = [&](int buf) {
#pragma unroll
        for (int it = 0; it < 2; it++) {
            int idx = tid + it*256;
            int m = idx >> 2, k4 = (idx & 3) * 4;
            As[buf][k4+0][m] = ra[it].x; As[buf][k4+1][m] = ra[it].y;
            As[buf][k4+2][m] = ra[it].z; As[buf][k4+3][m] = ra[it].w;
        }
    };
    auto ldW = [&](int k0) {
        if (TRANS_W) {
#pragma unroll
            for (int it = 0; it < 2; it++) {
                int idx = tid + it*256;
                int n = idx >> 2, k4 = (idx & 3) * 4;
                int gn = n0 + n;
                rw[it] = (gn < N) ? *reinterpret_cast<const float4*>(&W[(long long)gn*K + k0 + k4])
                                  : make_float4(0.f,0.f,0.f,0.f);
            }
        } else {
#pragma unroll
            for (int it = 0; it < 2; it++) {
                int idx = tid + it*256;
                int n4 = (idx & 31) * 4, k = idx >> 5;
                int gn = n0 + n4;
                rw[it] = (gn < N) ? *reinterpret_cast<const float4*>(&W[(long long)(k0 + k)*N + gn])
                                  : make_float4(0.f,0.f,0.f,0.f);
            }
        }
    };
    auto stW = [&](int buf) {
        if (TRANS_W) {
#pragma unroll
            for (int it = 0; it < 2; it++) {
                int idx = tid + it*256;
                int n = idx >> 2, k4 = (idx & 3) * 4;
                Ws[buf][k4+0][n] = rw[it].x; Ws[buf][k4+1][n] = rw[it].y;
                Ws[buf][k4+2][n] = rw[it].z; Ws[buf][k4+3][n] = rw[it].w;
            }
        } else {
#pragma unroll
            for (int it = 0; it < 2; it++) {
                int idx = tid + it*256;
                int n4 = (idx & 31) * 4, k = idx >> 5;
                *reinterpret_cast<float4*>(&Ws[buf][k][n4]) = rw[it];
            }
        }
    };

    float acc[8][8];
#pragma unroll
    for (int i = 0; i < 8; i++)
#pragma unroll
        for (int j = 0; j < 8; j++) acc[i][j] = 0.f;

    ldA(0); ldW(0); stA(0); stW(0);
    __syncthreads();

    const int nk = K / BK;
    for (int kt = 0; kt < nk; kt++) {
        const int cur = kt & 1;
        if (kt + 1 < nk) { ldA((kt+1)*BK); ldW((kt+1)*BK); }
#pragma unroll
        for (int k = 0; k < BK; k++) {
            float a[8], b[8];
            *reinterpret_cast<float4*>(&a[0]) = *reinterpret_cast<const float4*>(&As[cur][k][ty*4]);
            *reinterpret_cast<float4*>(&a[4]) = *reinterpret_cast<const float4*>(&As[cur][k][64 + ty*4]);
            *reinterpret_cast<float4*>(&b[0]) = *reinterpret_cast<const float4*>(&Ws[cur][k][tx*4]);
            *reinterpret_cast<float4*>(&b[4]) = *reinterpret_cast<const float4*>(&Ws[cur][k][64 + tx*4]);
#pragma unroll
            for (int i = 0; i < 8; i++)
#pragma unroll
                for (int j = 0; j < 8; j++) acc[i][j] += a[i]*b[j];
        }
        if (kt + 1 < nk) { stA(cur ^ 1); stW(cur ^ 1); }
        __syncthreads();
    }

#pragma unroll
    for (int i = 0; i < 8; i++) {
        int gm = m0 + ((i < 4) ? (ty*4 + i) : (64 + ty*4 + i - 4));
        if (gm >= M) continue;
#pragma unroll
        for (int j = 0; j < 8; j++) {
            int gn = n0 + ((j < 4) ? (tx*4 + j) : (64 + tx*4 + j - 4));
            if (gn >= N) continue;
            float v = acc[i][j];
            if (bias) v += bias[gn];
            long long ci = (long long)gm * N + gn;
            if (ACCUM) C[ci] += v;
            else       C[ci]  = v;
        }
    }
}

// ---------------- bidirectional GRU scan: 8-CTA clusters, DSMEM h-exchange ----------
// 128 CTAs = 16 clusters of 8; cluster = one (dir,batch) recurrence.
// CTA owns 32 units; warp owns 4 units, weight slice in registers (96 floats/thread).
// h exchange: CTA k publishes its 32 h values in own smem; hreg[k] is read directly
// from peer k's smem (unit lane+32k belongs to CTA k at offset lane).
// Sync: HW cluster barrier (release/acquire), double-buffered slots.
__global__ void __launch_bounds__(256) __cluster_dims__(8, 1, 1)
bigru_scan(
    const float* __restrict__ whf, const float* __restrict__ bhf,
    const float* __restrict__ whb, const float* __restrict__ bhb)
{
    __shared__ __align__(16) float h_sm[2][32];

    const int gidx = blockIdx.x >> 3;          // cluster id 0..15
    const int cid  = blockIdx.x & 7;           // rank in cluster
    const int dir  = gidx >> 3;                // 0 fwd, 1 bwd
    const int b    = gidx & 7;                 // batch

    const float* xg = dir ? g_xgb : g_xgf;
    const float* wh = dir ? whb : whf;
    const float* bh = dir ? bhb : bhf;

    const int tid = threadIdx.x;
    const int warp = tid >> 5, lane = tid & 31;
    const int jw = cid * 32 + warp * 4;        // this warp's unit base

    // peer smem addresses for h reads (rank k owns units [32k, 32k+32))
    const uint32_t my_h = smem_u32_(h_sm);
    uint32_t peer[8];
#pragma unroll
    for (int k = 0; k < 8; k++) peer[k] = mapa_u32_(my_h, (uint32_t)k) + lane * 4u;

    // weight slices: wreg[u*3+g][k] = Wh[g*HH + jw+u][lane + 32k]
    float wreg[12][8];
#pragma unroll
    for (int u = 0; u < 4; u++)
#pragma unroll
        for (int g = 0; g < 3; g++) {
            const float* wrow = wh + (long long)(g*HH + jw + u)*HH;
#pragma unroll
            for (int k = 0; k < 8; k++) wreg[u*3+g][k] = wrow[lane + 32*k];
        }

    float bh0 = 0.f, bh1 = 0.f, bh2 = 0.f;
    if (lane < 4) {
        bh0 = bh[0*HH + jw + lane];
        bh1 = bh[1*HH + jw + lane];
        bh2 = bh[2*HH + jw + lane];
    }

    float xr0 = 0.f, xr1 = 0.f, xr2 = 0.f;
    auto pre_x = [&](int t) {
        if (lane < 4) {
            int tt = dir ? (SS - 1 - t) : t;
            const float* xr = xg + ((long long)b*SS + tt) * (3*HH);
            xr0 = __ldcg(&xr[jw + lane]);
            xr1 = __ldcg(&xr[HH + jw + lane]);
            xr2 = __ldcg(&xr[2*HH + jw + lane]);
        }
    };
    pre_x(0);

    float hp = 0.f;    // carried h for (b, jw+lane), lanes 0..3

    for (int t = 0; t < SS; t++) {
        float hreg[8];
        if (t == 0) {
#pragma unroll
            for (int k = 0; k < 8; k++) hreg[k] = 0.f;
        } else {
            const uint32_t soff = (unsigned)(t & 1) * 128u;
#pragma unroll
            for (int k = 0; k < 8; k++) hreg[k] = ld_cluster_f32_(peer[k] + soff);
        }

        float dots[12];
#pragma unroll
        for (int i = 0; i < 12; i++) {
            float s = 0.f;
#pragma unroll
            for (int k = 0; k < 8; k++) s += wreg[i][k] * hreg[k];
#pragma unroll
            for (int off = 16; off; off >>= 1) s += __shfl_xor_sync(0xffffffffu, s, off);
            dots[i] = s;   // every lane holds the full sum
        }

        if (lane < 4) {
            float dr = dots[0], dz = dots[1], dn = dots[2];
            if (lane == 1) { dr = dots[3]; dz = dots[4];  dn = dots[5];  }
            if (lane == 2) { dr = dots[6]; dz = dots[7];  dn = dots[8];  }
            if (lane == 3) { dr = dots[9]; dz = dots[10]; dn = dots[11]; }
            float r = fsigmoid_(xr0 + dr + bh0);
            float z = fsigmoid_(xr1 + dz + bh1);
            float n = ftanh_(xr2 + r*(dn + bh2));
            float hnew = (1.f - z)*n + z*hp;
            hp = hnew;
            h_sm[(t + 1) & 1][warp*4 + lane] = hnew;   // publish for peers
            int tt = dir ? (SS - 1 - t) : t;
            long long mrow = (long long)b*SS + tt;
            g_bigru[mrow*H2 + (dir ? HH : 0) + jw + lane] = hnew;
            if (t == SS - 1) g_hiddencat[b*H2 + (dir ? 0 : HH) + jw + lane] = hnew;
        }
        if (t + 1 < SS) pre_x(t + 1);
        cluster_sync_();   // release smem writes, acquire for next step's peer reads
    }
}

// ---------------- unidirectional GRU scan: per-batch groups of 16 CTAs --------------
// 128 CTAs = 8 groups. CTA: 512 threads, 16 warps; warp owns 2 units (6 gate rows
// of 512), weight slice in registers (96 floats/thread). Barrier spans 16 CTAs.
__global__ void __launch_bounds__(512) uni_scan(
    const float* __restrict__ uwh, const float* __restrict__ ubh)
{
    const int gb  = blockIdx.x >> 4;           // batch 0..7
    const int cid = blockIdx.x & 15;

    const int tid = threadIdx.x;
    const int warp = tid >> 5, lane = tid & 31;
    const int jw = cid * 32 + warp * 2;        // this warp's unit base

    float wreg[6][16];
#pragma unroll
    for (int u = 0; u < 2; u++)
#pragma unroll
        for (int g = 0; g < 3; g++) {
            const float* wrow = uwh + (long long)(g*H2 + jw + u)*H2;
#pragma unroll
            for (int k = 0; k < 16; k++) wreg[u*3+g][k] = wrow[lane + 32*k];
        }

    float bh0 = 0.f, bh1 = 0.f, bh2 = 0.f;
    if (lane < 2) {
        bh0 = ubh[0*H2 + jw + lane];
        bh1 = ubh[1*H2 + jw + lane];
        bh2 = ubh[2*H2 + jw + lane];
    }

    // U[b,0] = hidden_cat  (one CTA per batch does its row)
    if (cid == 0) {
        for (int i = tid; i < H2; i += 512)
            g_U[((long long)gb*SS)*H2 + i] = g_hiddencat[gb*H2 + i];
    }

    float xr0 = 0.f, xr1 = 0.f, xr2 = 0.f;
    auto pre_x = [&](int t) {
        if (lane < 2) {
            const float* xr = g_xgu + ((long long)gb*SS + t) * (3*H2);
            xr0 = __ldcg(&xr[jw + lane]);
            xr1 = __ldcg(&xr[H2 + jw + lane]);
            xr2 = __ldcg(&xr[2*H2 + jw + lane]);
        }
    };
    pre_x(0);

    float hp = 0.f;

    for (int t = 0; t < SS; t++) {
        float hreg[16];
        if (t == 0) {
#pragma unroll
            for (int k = 0; k < 16; k++) hreg[k] = 0.f;
        } else {
            const float* cur = g_hu[t & 1] + gb*H2;
#pragma unroll
            for (int k = 0; k < 16; k++) hreg[k] = __ldcg(&cur[lane + 32*k]);
        }

        float dots[6];
#pragma unroll
        for (int i = 0; i < 6; i++) {
            float s = 0.f;
#pragma unroll
            for (int k = 0; k < 16; k++) s += wreg[i][k] * hreg[k];
#pragma unroll
            for (int off = 16; off; off >>= 1) s += __shfl_xor_sync(0xffffffffu, s, off);
            dots[i] = s;
        }

        if (lane < 2) {
            float dr = dots[0], dz = dots[1], dn = dots[2];
            if (lane == 1) { dr = dots[3]; dz = dots[4]; dn = dots[5]; }
            float r = fsigmoid_(xr0 + dr + bh0);
            float z = fsigmoid_(xr1 + dz + bh1);
            float n = ftanh_(xr2 + r*(dn + bh2));
            float hnew = (1.f - z)*n + z*hp;
            hp = hnew;
            long long mrow = (long long)gb*SS + t;
            g_hu[(t + 1) & 1][gb*H2 + jw + lane] = hnew;
            if (t < SS - 1) g_U[(mrow + 1)*H2 + jw + lane] = hnew;   // uni_out[:, :-1] -> U[:, 1:]
        }
        if (t + 1 < SS) pre_x(t + 1);
        grid_barrier(16, gb);
    }
}

// ---------------- softmax over last dim of energies ----------------
__global__ void softmax_kernel() {
    long long row = blockIdx.x;               // 0..8191
    float* p = g_energy + row * SS;
    __shared__ float red[256];
    int tid = threadIdx.x;
    float mx = -1e30f;
    for (int i = tid; i < SS; i += 256) mx = fmaxf(mx, p[i]);
    red[tid] = mx; __syncthreads();
    for (int s = 128; s; s >>= 1) { if (tid < s) red[tid] = fmaxf(red[tid], red[tid+s]); __syncthreads(); }
    mx = red[0]; __syncthreads();
    float sum = 0.f;
    for (int i = tid; i < SS; i += 256) { float e = expf(p[i] - mx); p[i] = e; sum += e; }
    red[tid] = sum; __syncthreads();
    for (int s = 128; s; s >>= 1) { if (tid < s) red[tid] += red[tid+s]; __syncthreads(); }
    float inv = 1.f / red[0];
    for (int i = tid; i < SS; i += 256) p[i] *= inv;
}

// ---------------- ft = cfc * sigmoid(gate) + bigru ----------------
__global__ void ft_kernel() {
    long long i = (long long)blockIdx.x * 256 + threadIdx.x;
    if (i < (long long)MROWS * H2) {
        g_ft[i] = g_cfc[i] * sigmoidf_(g_gate[i]) + g_bigru[i];
    }
}

// ---------------- host launcher ----------------
extern "C" void kernel_launch(void* const* d_in, const int* in_sizes, int n_in,
                              void* d_out, int out_size) {
    (void)in_sizes; (void)n_in; (void)out_size;
    const int*   tok       = (const int*)  d_in[0];
    const float* emb       = (const float*)d_in[2];
    const float* wi_f      = (const float*)d_in[3];
    const float* wh_f      = (const float*)d_in[4];
    const float* bi_f      = (const float*)d_in[5];
    const float* bh_f      = (const float*)d_in[6];
    const float* wi_b      = (const float*)d_in[7];
    const float* wh_b      = (const float*)d_in[8];
    const float* bi_b      = (const float*)d_in[9];
    const float* bh_b      = (const float*)d_in[10];
    const float* uwi       = (const float*)d_in[11];
    const float* uwh       = (const float*)d_in[12];
    const float* ubi       = (const float*)d_in[13];
    const float* ubh       = (const float*)d_in[14];
    const float* w_attn    = (const float*)d_in[15];
    const float* b_attn    = (const float*)d_in[16];
    const float* w_attn_fc = (const float*)d_in[17];
    const float* b_attn_fc = (const float*)d_in[18];
    const float* w_ht      = (const float*)d_in[19];
    const float* b_ht      = (const float*)d_in[20];
    const float* w_out     = (const float*)d_in[21];
    const float* b_out     = (const float*)d_in[22];
    float* out = (float*)d_out;

    float *px, *pxgf, *pxgb, *pbigru, *pxgu, *pU, *pE, *pctx, *pcfc, *pgate, *pft;
    cudaGetSymbolAddress((void**)&px,     g_x);
    cudaGetSymbolAddress((void**)&pxgf,   g_xgf);
    cudaGetSymbolAddress((void**)&pxgb,   g_xgb);
    cudaGetSymbolAddress((void**)&pbigru, g_bigru);
    cudaGetSymbolAddress((void**)&pxgu,   g_xgu);
    cudaGetSymbolAddress((void**)&pU,     g_U);
    cudaGetSymbolAddress((void**)&pE,     g_energy);
    cudaGetSymbolAddress((void**)&pctx,   g_context);
    cudaGetSymbolAddress((void**)&pcfc,   g_cfc);
    cudaGetSymbolAddress((void**)&pgate,  g_gate);
    cudaGetSymbolAddress((void**)&pft,    g_ft);

    // 1) embed
    embed_kernel<<<MROWS, EE>>>(tok, emb);

    // 2) input-gate projections (time-parallel)
    gemm_kernel<true,false><<<dim3(6, 64, 1), 256>>>(px, wi_f, bi_f, pxgf, MROWS, 3*HH, EE, 0, 0, 0);
    gemm_kernel<true,false><<<dim3(6, 64, 1), 256>>>(px, wi_b, bi_b, pxgb, MROWS, 3*HH, EE, 0, 0, 0);

    // 3) fwd+bwd recurrent scan (16 clusters of 8, DSMEM exchange)
    bigru_scan<<<128, 256>>>(wh_f, bh_f, wh_b, bh_b);

    // 4) uni input-gate projection
    gemm_kernel<true,false><<<dim3(12, 64, 1), 256>>>(pbigru, uwi, ubi, pxgu, MROWS, 3*H2, H2, 0, 0, 0);

    // 5) uni recurrent scan (8 independent 16-CTA barrier groups; assembles U)
    uni_scan<<<128, 512>>>(uwh, ubh);

    // 6) energies = U @ Y^T   (batched over B)
    gemm_kernel<true,false><<<dim3(8, 8, BB), 256>>>(pU, pbigru, nullptr, pE,
        SS, SS, H2, (long long)SS*H2, (long long)SS*H2, (long long)SS*SS);

    // 7) softmax over t
    softmax_kernel<<<MROWS, 256>>>();

    // 8) context = w @ Y      (batched over B, W non-transposed)
    gemm_kernel<false,false><<<dim3(4, 8, BB), 256>>>(pE, pbigru, nullptr, pctx,
        SS, H2, SS, (long long)SS*SS, (long long)SS*H2, (long long)SS*H2);

    // 9) cfc = context @ w_attn^T + b_attn
    gemm_kernel<true,false><<<dim3(4, 64, 1), 256>>>(pctx, w_attn, b_attn, pcfc, MROWS, H2, H2, 0, 0, 0);

    // 10) gate = cfc @ w_attn_fc^T + b_attn_fc ; then += Y @ w_ht^T + b_ht
    gemm_kernel<true,false><<<dim3(4, 64, 1), 256>>>(pcfc,   w_attn_fc, b_attn_fc, pgate, MROWS, H2, H2, 0, 0, 0);
    gemm_kernel<true,true ><<<dim3(4, 64, 1), 256>>>(pbigru, w_ht,      b_ht,      pgate, MROWS, H2, H2, 0, 0, 0);

    // 11) ft = cfc * sigmoid(gate) + Y
    ft_kernel<<<(MROWS*H2)/256, 256>>>();

    // 12) out = ft @ w_out^T + b_out
    gemm_kernel<true,false><<<dim3(1, 64, 1), 256>>>(pft, w_out, b_out, out, MROWS, COUT, H2, 0, 0, 0);
}

// round 10
// speedup vs baseline: 1.0920x; 1.0920x over previous
#include <cuda_runtime.h>
#include <math.h>
#include <stdint.h>

#define BB 8
#define SS 1024
#define EE 256
#define HH 256
#define H2 512
#define COUT 64
#define MROWS (BB*SS)   /* 8192 */

// ---------------- scratch (static __device__ arrays; no cudaMalloc) ----------------
__device__ __align__(16) float g_x[MROWS*EE];
__device__ __align__(16) float g_xgf[MROWS*3*HH];
__device__ __align__(16) float g_xgb[MROWS*3*HH];
__device__ __align__(16) float g_bigru[MROWS*H2];
__device__ __align__(16) float g_hiddencat[BB*H2];
__device__ __align__(16) float g_xgu[MROWS*3*H2];
__device__ __align__(16) float g_U[MROWS*H2];
__device__ __align__(16) float g_energy[BB*SS*SS];
__device__ __align__(16) float g_context[MROWS*H2];
__device__ __align__(16) float g_cfc[MROWS*H2];
__device__ __align__(16) float g_gate[MROWS*H2];
__device__ __align__(16) float g_ft[MROWS*H2];
__device__ __align__(16) float g_hu[2][BB*H2];

// ---------------- barrier state for uni (proven sense-reversing, per-group lines) ---
__device__ __align__(128) unsigned g_bar_count[16][32];
__device__ __align__(128) unsigned g_bar_gen[16][32];

__device__ __forceinline__ void grid_barrier(unsigned nctas, int idx) {
    __syncthreads();
    if (threadIdx.x == 0) {
        __threadfence();   // release
        unsigned my = *((volatile unsigned*)&g_bar_gen[idx][0]);
        unsigned t  = atomicAdd(&g_bar_count[idx][0], 1u);
        if (t == nctas - 1u) {
            g_bar_count[idx][0] = 0u;
            __threadfence();
            atomicExch(&g_bar_gen[idx][0], my + 1u);
        } else {
            while (*((volatile unsigned*)&g_bar_gen[idx][0]) == my) { }
            __threadfence(); // acquire
        }
    }
    __syncthreads();
}

// ---------------- cluster helpers ----------------
__device__ __forceinline__ uint32_t smem_u32_(const void* p) {
    uint32_t a;
    asm("{ .reg .u64 t; cvta.to.shared.u64 t, %1; cvt.u32.u64 %0, t; }" : "=r"(a) : "l"(p));
    return a;
}
__device__ __forceinline__ uint32_t mapa_u32_(uint32_t addr, uint32_t rank) {
    uint32_t r;
    asm("mapa.shared::cluster.u32 %0, %1, %2;" : "=r"(r) : "r"(addr), "r"(rank));
    return r;
}
__device__ __forceinline__ float ld_cluster_f32_(uint32_t addr) {
    float v;
    asm volatile("ld.shared::cluster.f32 %0, [%1];" : "=f"(v) : "r"(addr));
    return v;
}
__device__ __forceinline__ void cluster_sync_() {
    asm volatile("barrier.cluster.arrive.aligned;" ::: "memory");
    asm volatile("barrier.cluster.wait.aligned;"   ::: "memory");
}
__device__ __forceinline__ void mbar_init_(uint32_t addr, uint32_t cnt) {
    asm volatile("mbarrier.init.shared.b64 [%0], %1;" :: "r"(addr), "r"(cnt) : "memory");
}
// fire-and-forget arrive on a (possibly remote) cluster smem mbarrier; release at cluster scope
__device__ __forceinline__ void mbar_arrive_cluster_(uint32_t addr) {
    asm volatile("mbarrier.arrive.shared::cluster.b64 _, [%0];" :: "r"(addr) : "memory");
}
// wait for phase `parity` completion on local mbarrier; acquire at cluster scope
__device__ __forceinline__ void mbar_wait_parity_(uint32_t addr, uint32_t parity) {
    uint32_t done;
    asm volatile(
        "{\n\t.reg .pred p;\n\t"
        "mbarrier.try_wait.parity.acquire.cluster.shared::cta.b64 p, [%1], %2;\n\t"
        "selp.b32 %0, 1, 0, p;\n\t}"
        : "=r"(done) : "r"(addr), "r"(parity) : "memory");
    while (!done) {
        asm volatile(
            "{\n\t.reg .pred p;\n\t"
            "mbarrier.try_wait.parity.acquire.cluster.shared::cta.b64 p, [%1], %2, 0x989680;\n\t"
            "selp.b32 %0, 1, 0, p;\n\t}"
            : "=r"(done) : "r"(addr), "r"(parity) : "memory");
    }
}

// fast gate functions (|err| ~1e-7, threshold is 1e-3)
__device__ __forceinline__ float fsigmoid_(float x) { return 1.f/(1.f + __expf(-x)); }
__device__ __forceinline__ float ftanh_(float x)    { return 1.f - 2.f/(__expf(2.f*x) + 1.f); }
__device__ __forceinline__ float sigmoidf_(float x) { return 1.f/(1.f + expf(-x)); }

// ---------------- embedding gather ----------------
__global__ void embed_kernel(const int* __restrict__ tok, const float* __restrict__ emb) {
    int m = blockIdx.x;
    int e = threadIdx.x;                       // EE == 256 == blockDim
    g_x[m*EE + e] = emb[(long long)tok[m]*EE + e];
}

// ---------------- fp32 GEMM, double-buffered, 2 CTAs/SM: C = A @ op(W) + bias -------
template<bool TRANS_W, bool ACCUM>
__global__ void __launch_bounds__(256, 2) gemm_kernel(
    const float* __restrict__ A, const float* __restrict__ W,
    const float* __restrict__ bias, float* __restrict__ C,
    int M, int N, int K,
    long long sA, long long sW, long long sC)
{
    constexpr int BM = 128, BN = 128, BK = 16;
    __shared__ float As[2][BK][BM];
    __shared__ float Ws[2][BK][BN];

    A += (long long)blockIdx.z * sA;
    W += (long long)blockIdx.z * sW;
    C += (long long)blockIdx.z * sC;

    const int m0 = blockIdx.y * BM, n0 = blockIdx.x * BN;
    const int tid = threadIdx.x;
    const int tx = tid & 15, ty = tid >> 4;

    float4 ra[2], rw[2];

    auto ldA = [&](int k0) {
#pragma unroll
        for (int it = 0; it < 2; it++) {
            int idx = tid + it*256;
            int m = idx >> 2, k4 = (idx & 3) * 4;
            ra[it] = *reinterpret_cast<const float4*>(&A[(long long)(m0 + m)*K + k0 + k4]);
        }
    };
    auto stA = [&](int buf) {
#pragma unroll
        for (int it = 0; it < 2; it++) {
            int idx = tid + it*256;
            int m = idx >> 2, k4 = (idx & 3) * 4;
            As[buf][k4+0][m] = ra[it].x; As[buf][k4+1][m] = ra[it].y;
            As[buf][k4+2][m] = ra[it].z; As[buf][k4+3][m] = ra[it].w;
        }
    };
    auto ldW = [&](int k0) {
        if (TRANS_W) {
#pragma unroll
            for (int it = 0; it < 2; it++) {
                int idx = tid + it*256;
                int n = idx >> 2, k4 = (idx & 3) * 4;
                int gn = n0 + n;
                rw[it] = (gn < N) ? *reinterpret_cast<const float4*>(&W[(long long)gn*K + k0 + k4])
                                  : make_float4(0.f,0.f,0.f,0.f);
            }
        } else {
#pragma unroll
            for (int it = 0; it < 2; it++) {
                int idx = tid + it*256;
                int n4 = (idx & 31) * 4, k = idx >> 5;
                int gn = n0 + n4;
                rw[it] = (gn < N) ? *reinterpret_cast<const float4*>(&W[(long long)(k0 + k)*N + gn])
                                  : make_float4(0.f,0.f,0.f,0.f);
            }
        }
    };
    auto stW = [&](int buf) {
        if (TRANS_W) {
#pragma unroll
            for (int it = 0; it < 2; it++) {
                int idx = tid + it*256;
                int n = idx >> 2, k4 = (idx & 3) * 4;
                Ws[buf][k4+0][n] = rw[it].x; Ws[buf][k4+1][n] = rw[it].y;
                Ws[buf][k4+2][n] = rw[it].z; Ws[buf][k4+3][n] = rw[it].w;
            }
        } else {
#pragma unroll
            for (int it = 0; it < 2; it++) {
                int idx = tid + it*256;
                int n4 = (idx & 31) * 4, k = idx >> 5;
                *reinterpret_cast<float4*>(&Ws[buf][k][n4]) = rw[it];
            }
        }
    };

    float acc[8][8];
#pragma unroll
    for (int i = 0; i < 8; i++)
#pragma unroll
        for (int j = 0; j < 8; j++) acc[i][j] = 0.f;

    ldA(0); ldW(0); stA(0); stW(0);
    __syncthreads();

    const int nk = K / BK;
    for (int kt = 0; kt < nk; kt++) {
        const int cur = kt & 1;
        if (kt + 1 < nk) { ldA((kt+1)*BK); ldW((kt+1)*BK); }
#pragma unroll
        for (int k = 0; k < BK; k++) {
            float a[8], b[8];
            *reinterpret_cast<float4*>(&a[0]) = *reinterpret_cast<const float4*>(&As[cur][k][ty*4]);
            *reinterpret_cast<float4*>(&a[4]) = *reinterpret_cast<const float4*>(&As[cur][k][64 + ty*4]);
            *reinterpret_cast<float4*>(&b[0]) = *reinterpret_cast<const float4*>(&Ws[cur][k][tx*4]);
            *reinterpret_cast<float4*>(&b[4]) = *reinterpret_cast<const float4*>(&Ws[cur][k][64 + tx*4]);
#pragma unroll
            for (int i = 0; i < 8; i++)
#pragma unroll
                for (int j = 0; j < 8; j++) acc[i][j] += a[i]*b[j];
        }
        if (kt + 1 < nk) { stA(cur ^ 1); stW(cur ^ 1); }
        __syncthreads();
    }

#pragma unroll
    for (int i = 0; i < 8; i++) {
        int gm = m0 + ((i < 4) ? (ty*4 + i) : (64 + ty*4 + i - 4));
        if (gm >= M) continue;
#pragma unroll
        for (int j = 0; j < 8; j++) {
            int gn = n0 + ((j < 4) ? (tx*4 + j) : (64 + tx*4 + j - 4));
            if (gn >= N) continue;
            float v = acc[i][j];
            if (bias) v += bias[gn];
            long long ci = (long long)gm * N + gn;
            if (ACCUM) C[ci] += v;
            else       C[ci]  = v;
        }
    }
}

// ---------------- bidirectional GRU scan: 8-CTA clusters, DSMEM h + mbarrier sync ---
// 128 CTAs = 16 clusters of 8; cluster = one (dir,batch) recurrence.
// CTA owns 32 units; warp owns 4 units, weight slice in registers (96 floats/thread).
// Sync: per-CTA smem mbarrier (count 8). Each step every CTA fires 8 fire-and-forget
// cluster arrives (release), then try_wait.parity (acquire) on its own mbarrier.
// No barrier.cluster in the loop (no 490-cyc UCGABAR, no per-step L1D flush).
__global__ void __launch_bounds__(256) __cluster_dims__(8, 1, 1)
bigru_scan(
    const float* __restrict__ whf, const float* __restrict__ bhf,
    const float* __restrict__ whb, const float* __restrict__ bhb)
{
    __shared__ __align__(16) float h_sm[2][32];
    __shared__ __align__(8)  unsigned long long mbar_store;

    const int gidx = blockIdx.x >> 3;          // cluster id 0..15
    const int cid  = blockIdx.x & 7;           // rank in cluster
    const int dir  = gidx >> 3;                // 0 fwd, 1 bwd
    const int b    = gidx & 7;                 // batch

    const float* xg = dir ? g_xgb : g_xgf;
    const float* wh = dir ? whb : whf;
    const float* bh = dir ? bhb : bhf;

    const int tid = threadIdx.x;
    const int warp = tid >> 5, lane = tid & 31;
    const int jw = cid * 32 + warp * 4;        // this warp's unit base

    // peer smem addresses (rank k owns units [32k, 32k+32))
    const uint32_t my_h = smem_u32_(h_sm);
    const uint32_t my_m = smem_u32_(&mbar_store);
    uint32_t peer_h[8], peer_m[8];
#pragma unroll
    for (int k = 0; k < 8; k++) {
        peer_h[k] = mapa_u32_(my_h, (uint32_t)k) + lane * 4u;
        peer_m[k] = mapa_u32_(my_m, (uint32_t)k);
    }

    if (tid == 0) mbar_init_(my_m, 8);

    // weight slices: wreg[u*3+g][k] = Wh[g*HH + jw+u][lane + 32k]
    float wreg[12][8];
#pragma unroll
    for (int u = 0; u < 4; u++)
#pragma unroll
        for (int g = 0; g < 3; g++) {
            const float* wrow = wh + (long long)(g*HH + jw + u)*HH;
#pragma unroll
            for (int k = 0; k < 8; k++) wreg[u*3+g][k] = wrow[lane + 32*k];
        }

    float bh0 = 0.f, bh1 = 0.f, bh2 = 0.f;
    if (lane < 4) {
        bh0 = bh[0*HH + jw + lane];
        bh1 = bh[1*HH + jw + lane];
        bh2 = bh[2*HH + jw + lane];
    }

    float xr0 = 0.f, xr1 = 0.f, xr2 = 0.f;
    auto pre_x = [&](int t) {
        if (lane < 4) {
            int tt = dir ? (SS - 1 - t) : t;
            const float* xr = xg + ((long long)b*SS + tt) * (3*HH);
            xr0 = __ldcg(&xr[jw + lane]);
            xr1 = __ldcg(&xr[HH + jw + lane]);
            xr2 = __ldcg(&xr[2*HH + jw + lane]);
        }
    };
    pre_x(0);

    cluster_sync_();   // one-time: all mbarriers initialized before any arrives

    float hp = 0.f;    // carried h for (b, jw+lane), lanes 0..3

    for (int t = 0; t < SS; t++) {
        float hreg[8];
        if (t == 0) {
#pragma unroll
            for (int k = 0; k < 8; k++) hreg[k] = 0.f;
        } else {
            const uint32_t soff = (unsigned)(t & 1) * 128u;
#pragma unroll
            for (int k = 0; k < 8; k++) hreg[k] = ld_cluster_f32_(peer_h[k] + soff);
        }

        float dots[12];
#pragma unroll
        for (int i = 0; i < 12; i++) {
            float s = 0.f;
#pragma unroll
            for (int k = 0; k < 8; k++) s += wreg[i][k] * hreg[k];
#pragma unroll
            for (int off = 16; off; off >>= 1) s += __shfl_xor_sync(0xffffffffu, s, off);
            dots[i] = s;   // every lane holds the full sum
        }

        if (lane < 4) {
            float dr = dots[0], dz = dots[1], dn = dots[2];
            if (lane == 1) { dr = dots[3]; dz = dots[4];  dn = dots[5];  }
            if (lane == 2) { dr = dots[6]; dz = dots[7];  dn = dots[8];  }
            if (lane == 3) { dr = dots[9]; dz = dots[10]; dn = dots[11]; }
            float r = fsigmoid_(xr0 + dr + bh0);
            float z = fsigmoid_(xr1 + dz + bh1);
            float n = ftanh_(xr2 + r*(dn + bh2));
            float hnew = (1.f - z)*n + z*hp;
            hp = hnew;
            h_sm[(t + 1) & 1][warp*4 + lane] = hnew;   // publish for peers
            int tt = dir ? (SS - 1 - t) : t;
            long long mrow = (long long)b*SS + tt;
            g_bigru[mrow*H2 + (dir ? HH : 0) + jw + lane] = hnew;
            if (t == SS - 1) g_hiddencat[b*H2 + (dir ? 0 : HH) + jw + lane] = hnew;
        }

        if (t + 1 < SS) {
            __syncthreads();                  // order publishes before arrives
            if (tid == 0) {
#pragma unroll
                for (int k = 0; k < 8; k++) mbar_arrive_cluster_(peer_m[k]);
            }
            pre_x(t + 1);                     // overlap xg fetch with peers' arrivals
            mbar_wait_parity_(my_m, (unsigned)(t & 1));
        }
    }
}

// ---------------- unidirectional GRU scan: per-batch groups of 16 CTAs --------------
// 128 CTAs = 8 groups. CTA: 512 threads, 16 warps; warp owns 2 units (6 gate rows
// of 512), weight slice in registers (96 floats/thread). Barrier spans 16 CTAs.
__global__ void __launch_bounds__(512) uni_scan(
    const float* __restrict__ uwh, const float* __restrict__ ubh)
{
    const int gb  = blockIdx.x >> 4;           // batch 0..7
    const int cid = blockIdx.x & 15;

    const int tid = threadIdx.x;
    const int warp = tid >> 5, lane = tid & 31;
    const int jw = cid * 32 + warp * 2;        // this warp's unit base

    float wreg[6][16];
#pragma unroll
    for (int u = 0; u < 2; u++)
#pragma unroll
        for (int g = 0; g < 3; g++) {
            const float* wrow = uwh + (long long)(g*H2 + jw + u)*H2;
#pragma unroll
            for (int k = 0; k < 16; k++) wreg[u*3+g][k] = wrow[lane + 32*k];
        }

    float bh0 = 0.f, bh1 = 0.f, bh2 = 0.f;
    if (lane < 2) {
        bh0 = ubh[0*H2 + jw + lane];
        bh1 = ubh[1*H2 + jw + lane];
        bh2 = ubh[2*H2 + jw + lane];
    }

    // U[b,0] = hidden_cat  (one CTA per batch does its row)
    if (cid == 0) {
        for (int i = tid; i < H2; i += 512)
            g_U[((long long)gb*SS)*H2 + i] = g_hiddencat[gb*H2 + i];
    }

    float xr0 = 0.f, xr1 = 0.f, xr2 = 0.f;
    auto pre_x = [&](int t) {
        if (lane < 2) {
            const float* xr = g_xgu + ((long long)gb*SS + t) * (3*H2);
            xr0 = __ldcg(&xr[jw + lane]);
            xr1 = __ldcg(&xr[H2 + jw + lane]);
            xr2 = __ldcg(&xr[2*H2 + jw + lane]);
        }
    };
    pre_x(0);

    float hp = 0.f;

    for (int t = 0; t < SS; t++) {
        float hreg[16];
        if (t == 0) {
#pragma unroll
            for (int k = 0; k < 16; k++) hreg[k] = 0.f;
        } else {
            const float* cur = g_hu[t & 1] + gb*H2;
#pragma unroll
            for (int k = 0; k < 16; k++) hreg[k] = __ldcg(&cur[lane + 32*k]);
        }

        float dots[6];
#pragma unroll
        for (int i = 0; i < 6; i++) {
            float s = 0.f;
#pragma unroll
            for (int k = 0; k < 16; k++) s += wreg[i][k] * hreg[k];
#pragma unroll
            for (int off = 16; off; off >>= 1) s += __shfl_xor_sync(0xffffffffu, s, off);
            dots[i] = s;
        }

        if (lane < 2) {
            float dr = dots[0], dz = dots[1], dn = dots[2];
            if (lane == 1) { dr = dots[3]; dz = dots[4]; dn = dots[5]; }
            float r = fsigmoid_(xr0 + dr + bh0);
            float z = fsigmoid_(xr1 + dz + bh1);
            float n = ftanh_(xr2 + r*(dn + bh2));
            float hnew = (1.f - z)*n + z*hp;
            hp = hnew;
            long long mrow = (long long)gb*SS + t;
            g_hu[(t + 1) & 1][gb*H2 + jw + lane] = hnew;
            if (t < SS - 1) g_U[(mrow + 1)*H2 + jw + lane] = hnew;   // uni_out[:, :-1] -> U[:, 1:]
        }
        if (t + 1 < SS) pre_x(t + 1);
        grid_barrier(16, gb);
    }
}

// ---------------- softmax over last dim of energies ----------------
__global__ void softmax_kernel() {
    long long row = blockIdx.x;               // 0..8191
    float* p = g_energy + row * SS;
    __shared__ float red[256];
    int tid = threadIdx.x;
    float mx = -1e30f;
    for (int i = tid; i < SS; i += 256) mx = fmaxf(mx, p[i]);
    red[tid] = mx; __syncthreads();
    for (int s = 128; s; s >>= 1) { if (tid < s) red[tid] = fmaxf(red[tid], red[tid+s]); __syncthreads(); }
    mx = red[0]; __syncthreads();
    float sum = 0.f;
    for (int i = tid; i < SS; i += 256) { float e = expf(p[i] - mx); p[i] = e; sum += e; }
    red[tid] = sum; __syncthreads();
    for (int s = 128; s; s >>= 1) { if (tid < s) red[tid] += red[tid+s]; __syncthreads(); }
    float inv = 1.f / red[0];
    for (int i = tid; i < SS; i += 256) p[i] *= inv;
}

// ---------------- ft = cfc * sigmoid(gate) + bigru ----------------
__global__ void ft_kernel() {
    long long i = (long long)blockIdx.x * 256 + threadIdx.x;
    if (i < (long long)MROWS * H2) {
        g_ft[i] = g_cfc[i] * sigmoidf_(g_gate[i]) + g_bigru[i];
    }
}

// ---------------- host launcher ----------------
extern "C" void kernel_launch(void* const* d_in, const int* in_sizes, int n_in,
                              void* d_out, int out_size) {
    (void)in_sizes; (void)n_in; (void)out_size;
    const int*   tok       = (const int*)  d_in[0];
    const float* emb       = (const float*)d_in[2];
    const float* wi_f      = (const float*)d_in[3];
    const float* wh_f      = (const float*)d_in[4];
    const float* bi_f      = (const float*)d_in[5];
    const float* bh_f      = (const float*)d_in[6];
    const float* wi_b      = (const float*)d_in[7];
    const float* wh_b      = (const float*)d_in[8];
    const float* bi_b      = (const float*)d_in[9];
    const float* bh_b      = (const float*)d_in[10];
    const float* uwi       = (const float*)d_in[11];
    const float* uwh       = (const float*)d_in[12];
    const float* ubi       = (const float*)d_in[13];
    const float* ubh       = (const float*)d_in[14];
    const float* w_attn    = (const float*)d_in[15];
    const float* b_attn    = (const float*)d_in[16];
    const float* w_attn_fc = (const float*)d_in[17];
    const float* b_attn_fc = (const float*)d_in[18];
    const float* w_ht      = (const float*)d_in[19];
    const float* b_ht      = (const float*)d_in[20];
    const float* w_out     = (const float*)d_in[21];
    const float* b_out     = (const float*)d_in[22];
    float* out = (float*)d_out;

    float *px, *pxgf, *pxgb, *pbigru, *pxgu, *pU, *pE, *pctx, *pcfc, *pgate, *pft;
    cudaGetSymbolAddress((void**)&px,     g_x);
    cudaGetSymbolAddress((void**)&pxgf,   g_xgf);
    cudaGetSymbolAddress((void**)&pxgb,   g_xgb);
    cudaGetSymbolAddress((void**)&pbigru, g_bigru);
    cudaGetSymbolAddress((void**)&pxgu,   g_xgu);
    cudaGetSymbolAddress((void**)&pU,     g_U);
    cudaGetSymbolAddress((void**)&pE,     g_energy);
    cudaGetSymbolAddress((void**)&pctx,   g_context);
    cudaGetSymbolAddress((void**)&pcfc,   g_cfc);
    cudaGetSymbolAddress((void**)&pgate,  g_gate);
    cudaGetSymbolAddress((void**)&pft,    g_ft);

    // 1) embed
    embed_kernel<<<MROWS, EE>>>(tok, emb);

    // 2) input-gate projections (time-parallel)
    gemm_kernel<true,false><<<dim3(6, 64, 1), 256>>>(px, wi_f, bi_f, pxgf, MROWS, 3*HH, EE, 0, 0, 0);
    gemm_kernel<true,false><<<dim3(6, 64, 1), 256>>>(px, wi_b, bi_b, pxgb, MROWS, 3*HH, EE, 0, 0, 0);

    // 3) fwd+bwd recurrent scan (16 clusters of 8, DSMEM h + mbarrier signaling)
    bigru_scan<<<128, 256>>>(wh_f, bh_f, wh_b, bh_b);

    // 4) uni input-gate projection
    gemm_kernel<true,false><<<dim3(12, 64, 1), 256>>>(pbigru, uwi, ubi, pxgu, MROWS, 3*H2, H2, 0, 0, 0);

    // 5) uni recurrent scan (8 independent 16-CTA barrier groups; assembles U)
    uni_scan<<<128, 512>>>(uwh, ubh);

    // 6) energies = U @ Y^T   (batched over B)
    gemm_kernel<true,false><<<dim3(8, 8, BB), 256>>>(pU, pbigru, nullptr, pE,
        SS, SS, H2, (long long)SS*H2, (long long)SS*H2, (long long)SS*SS);

    // 7) softmax over t
    softmax_kernel<<<MROWS, 256>>>();

    // 8) context = w @ Y      (batched over B, W non-transposed)
    gemm_kernel<false,false><<<dim3(4, 8, BB), 256>>>(pE, pbigru, nullptr, pctx,
        SS, H2, SS, (long long)SS*SS, (long long)SS*H2, (long long)SS*H2);

    // 9) cfc = context @ w_attn^T + b_attn
    gemm_kernel<true,false><<<dim3(4, 64, 1), 256>>>(pctx, w_attn, b_attn, pcfc, MROWS, H2, H2, 0, 0, 0);

    // 10) gate = cfc @ w_attn_fc^T + b_attn_fc ; then += Y @ w_ht^T + b_ht
    gemm_kernel<true,false><<<dim3(4, 64, 1), 256>>>(pcfc,   w_attn_fc, b_attn_fc, pgate, MROWS, H2, H2, 0, 0, 0);
    gemm_kernel<true,true ><<<dim3(4, 64, 1), 256>>>(pbigru, w_ht,      b_ht,      pgate, MROWS, H2, H2, 0, 0, 0);

    // 11) ft = cfc * sigmoid(gate) + Y
    ft_kernel<<<(MROWS*H2)/256, 256>>>();

    // 12) out = ft @ w_out^T + b_out
    gemm_kernel<true,false><<<dim3(1, 64, 1), 256>>>(pft, w_out, b_out, out, MROWS, COUT, H2, 0, 0, 0);
}